// round 5
// baseline (speedup 1.0000x reference)
#include <cuda_runtime.h>
#include <stdint.h>

#define NMAX 100000
#define EMAX 1600000
#define D 64

// Scratch (static device globals: allocation-free, graph-capturable)
__device__ float g_xw[(size_t)NMAX * D];
__device__ float g_deg[NMAX];
__device__ float g_dinv[NMAX];

// ---------------------------------------------------------------------------
// K0: xw = x @ W   (x: [n,64], W: [64,64])
// Block: 256 threads, 64 rows per block. 4 rows x 4 cols register blocking.
// ---------------------------------------------------------------------------
__global__ void __launch_bounds__(256) gemm64_kernel(
    const float* __restrict__ x, const float* __restrict__ W, int n)
{
    __shared__ float  sX[64][65];   // padded: kills bank conflicts on column reads
    __shared__ float4 sW[64][16];   // W[k][c4] as float4

    const int t = threadIdx.x;
    const int rowBase = blockIdx.x * 64;

    // Load W (4096 floats = 1024 float4, 4 per thread)
    {
        const float4* W4 = (const float4*)W;
        #pragma unroll
        for (int i = 0; i < 4; i++) {
            int idx = t + i * 256;            // 0..1023
            sW[idx >> 4][idx & 15] = W4[idx];
        }
    }
    // Load 64 rows of x (1024 float4, 4 per thread)
    {
        #pragma unroll
        for (int i = 0; i < 4; i++) {
            int idx = t + i * 256;
            int r = idx >> 4, c4 = idx & 15;
            int row = rowBase + r;
            float4 v = make_float4(0.f, 0.f, 0.f, 0.f);
            if (row < n) v = ((const float4*)(x + (size_t)row * D))[c4];
            sX[r][c4 * 4 + 0] = v.x;
            sX[r][c4 * 4 + 1] = v.y;
            sX[r][c4 * 4 + 2] = v.z;
            sX[r][c4 * 4 + 3] = v.w;
        }
    }
    __syncthreads();

    const int c4 = t & 15;   // which float4 column group
    const int r0 = t >> 4;   // 0..15; rows r0, r0+16, r0+32, r0+48

    float4 acc[4];
    #pragma unroll
    for (int r = 0; r < 4; r++) acc[r] = make_float4(0.f, 0.f, 0.f, 0.f);

    #pragma unroll
    for (int k = 0; k < 64; k++) {
        float4 w = sW[k][c4];
        #pragma unroll
        for (int r = 0; r < 4; r++) {
            float xv = sX[r0 + 16 * r][k];
            acc[r].x += xv * w.x;
            acc[r].y += xv * w.y;
            acc[r].z += xv * w.z;
            acc[r].w += xv * w.w;
        }
    }

    #pragma unroll
    for (int r = 0; r < 4; r++) {
        int row = rowBase + r0 + 16 * r;
        if (row < n)
            ((float4*)(g_xw + (size_t)row * D))[c4] = acc[r];
    }
}

// ---------------------------------------------------------------------------
// K1: deg[i] = 1 (self-loop). MUST run every launch: graph replay re-runs the
// atomic accumulation in K2, so deg has to be reset for determinism.
// ---------------------------------------------------------------------------
__global__ void deg_init_kernel(int n)
{
    int i = blockIdx.x * blockDim.x + threadIdx.x;
    if (i < n) g_deg[i] = 1.0f;
}

// ---------------------------------------------------------------------------
// K2: deg[dst[e]] += 1 for each edge
// ---------------------------------------------------------------------------
__global__ void deg_count_kernel(const int* __restrict__ dst, int E)
{
    int e = blockIdx.x * blockDim.x + threadIdx.x;
    if (e < E) {
        int d = __ldg(&dst[e]);
        atomicAdd(&g_deg[d], 1.0f);
    }
}

// ---------------------------------------------------------------------------
// K3: dinv[i] = rsqrt(deg[i])   (deg >= 1 always due to self-loop)
// ---------------------------------------------------------------------------
__global__ void dinv_kernel(int n)
{
    int i = blockIdx.x * blockDim.x + threadIdx.x;
    if (i < n) g_dinv[i] = rsqrtf(g_deg[i]);
}

// ---------------------------------------------------------------------------
// K4: out[i] = xw[i] * dinv[i]^2 + b   (self-loop term + bias; initializes out)
// One float4 per thread: 16 threads per row.
// ---------------------------------------------------------------------------
__global__ void out_init_kernel(const float* __restrict__ b,
                                float* __restrict__ out, int n)
{
    int idx = blockIdx.x * blockDim.x + threadIdx.x;
    int i = idx >> 4, c4 = idx & 15;
    if (i < n) {
        float di = g_dinv[i];
        float s = di * di;
        float4 v  = ((const float4*)(g_xw + (size_t)i * D))[c4];
        float4 bb = ((const float4*)b)[c4];
        float4 o;
        o.x = v.x * s + bb.x;
        o.y = v.y * s + bb.y;
        o.z = v.z * s + bb.z;
        o.w = v.w * s + bb.w;
        ((float4*)(out + (size_t)i * D))[c4] = o;
    }
}

// ---------------------------------------------------------------------------
// K5: edge scatter: out[dst] += xw[src] * dinv[src]*dinv[dst]
// 16 threads per edge, one red.global.add.v4.f32 per thread (16B, aligned).
// ---------------------------------------------------------------------------
__device__ __forceinline__ void red_add_v4(float* dp, float a, float b, float c, float d)
{
#if !defined(__CUDA_ARCH__) || __CUDA_ARCH__ >= 900
    asm volatile(
        "red.global.add.v4.f32 [%0], {%1, %2, %3, %4};"
        :: "l"(dp), "f"(a), "f"(b), "f"(c), "f"(d)
        : "memory");
#else
    atomicAdd(dp + 0, a);
    atomicAdd(dp + 1, b);
    atomicAdd(dp + 2, c);
    atomicAdd(dp + 3, d);
#endif
}

__global__ void __launch_bounds__(256) scatter_kernel(
    const int* __restrict__ ei, float* __restrict__ out, int E)
{
    unsigned int t = blockIdx.x * 256u + threadIdx.x;
    int e    = (int)(t >> 4);
    int lane = (int)(t & 15);
    if (e >= E) return;

    int s = __ldg(&ei[e]);
    int d = __ldg(&ei[E + e]);
    float c = g_dinv[s] * g_dinv[d];

    float4 v = ((const float4*)(g_xw + (size_t)s * D))[lane];
    float* dp = out + (size_t)d * D + lane * 4;

    red_add_v4(dp, v.x * c, v.y * c, v.z * c, v.w * c);
}

// ---------------------------------------------------------------------------
// Launch
// Inputs (metadata order): x [n*64] f32, edge_index [2*E] int32, W [64*64] f32,
//                          b [64] f32. Output: [n*64] f32.
// ---------------------------------------------------------------------------
extern "C" void kernel_launch(void* const* d_in, const int* in_sizes, int n_in,
                              void* d_out, int out_size)
{
    const float* x  = (const float*)d_in[0];
    const int*   ei = (const int*)d_in[1];
    const float* W  = (const float*)d_in[2];
    const float* b  = (const float*)d_in[3];
    float*       out = (float*)d_out;

    const int n = in_sizes[0] / D;       // 100000
    const int E = in_sizes[1] / 2;       // 1600000

    // K0: projection
    gemm64_kernel<<<(n + 63) / 64, 256>>>(x, W, n);

    // K1-K3: degrees / normalization
    deg_init_kernel<<<(n + 255) / 256, 256>>>(n);
    deg_count_kernel<<<(E + 255) / 256, 256>>>(ei + E, E);  // dst row
    dinv_kernel<<<(n + 255) / 256, 256>>>(n);

    // K4: self-loop + bias (initializes out)
    {
        int total = n * 16;
        out_init_kernel<<<(total + 255) / 256, 256>>>(b, out, n);
    }

    // K5: edge scatter
    {
        long long total = (long long)E * 16;
        int blocks = (int)((total + 255) / 256);
        scatter_kernel<<<blocks, 256>>>(ei, out, E);
    }
}

// round 6
// speedup vs baseline: 1.0111x; 1.0111x over previous
#include <cuda_runtime.h>
#include <stdint.h>

#define NMAX 100000
#define EMAX 1600000
#define D 64

// Scratch (static device globals: allocation-free, graph-capturable).
// g_deg starts zero-initialized and is RESET to zero by fused_node_kernel each
// launch, so graph replays are deterministic.
__device__ float g_xw[(size_t)NMAX * D];
__device__ float g_deg[NMAX];
__device__ float g_dinv[NMAX];

// ---------------------------------------------------------------------------
// K0: xw = x @ W   (x: [n,64], W: [64,64])
// Block: 256 threads, 64 rows per block. 4 rows x 4 cols register blocking.
// ---------------------------------------------------------------------------
__global__ void __launch_bounds__(256) gemm64_kernel(
    const float* __restrict__ x, const float* __restrict__ W, int n)
{
    __shared__ float  sX[64][65];   // padded: kills bank conflicts on column reads
    __shared__ float4 sW[64][16];   // W[k][c4] as float4

    const int t = threadIdx.x;
    const int rowBase = blockIdx.x * 64;

    // Load W (4096 floats = 1024 float4, 4 per thread)
    {
        const float4* W4 = (const float4*)W;
        #pragma unroll
        for (int i = 0; i < 4; i++) {
            int idx = t + i * 256;            // 0..1023
            sW[idx >> 4][idx & 15] = W4[idx];
        }
    }
    // Load 64 rows of x (1024 float4, 4 per thread)
    {
        #pragma unroll
        for (int i = 0; i < 4; i++) {
            int idx = t + i * 256;
            int r = idx >> 4, c4 = idx & 15;
            int row = rowBase + r;
            float4 v = make_float4(0.f, 0.f, 0.f, 0.f);
            if (row < n) v = ((const float4*)(x + (size_t)row * D))[c4];
            sX[r][c4 * 4 + 0] = v.x;
            sX[r][c4 * 4 + 1] = v.y;
            sX[r][c4 * 4 + 2] = v.z;
            sX[r][c4 * 4 + 3] = v.w;
        }
    }
    __syncthreads();

    const int c4 = t & 15;   // which float4 column group
    const int r0 = t >> 4;   // 0..15; rows r0, r0+16, r0+32, r0+48

    float4 acc[4];
    #pragma unroll
    for (int r = 0; r < 4; r++) acc[r] = make_float4(0.f, 0.f, 0.f, 0.f);

    #pragma unroll
    for (int k = 0; k < 64; k++) {
        float4 w = sW[k][c4];
        #pragma unroll
        for (int r = 0; r < 4; r++) {
            float xv = sX[r0 + 16 * r][k];
            acc[r].x += xv * w.x;
            acc[r].y += xv * w.y;
            acc[r].z += xv * w.z;
            acc[r].w += xv * w.w;
        }
    }

    #pragma unroll
    for (int r = 0; r < 4; r++) {
        int row = rowBase + r0 + 16 * r;
        if (row < n)
            ((float4*)(g_xw + (size_t)row * D))[c4] = acc[r];
    }
}

// ---------------------------------------------------------------------------
// K1: deg[dst[e]] += 1 for each edge (deg starts at 0; self-loop folded into
// the rsqrt in the fused node kernel).
// ---------------------------------------------------------------------------
__global__ void deg_count_kernel(const int* __restrict__ dst, int E)
{
    int e = blockIdx.x * blockDim.x + threadIdx.x;
    if (e < E) {
        int d = __ldg(&dst[e]);
        atomicAdd(&g_deg[d], 1.0f);
    }
}

// ---------------------------------------------------------------------------
// K2 (fused): per node i:
//   d        = rsqrt(deg[i] + 1)         (self-loop included)
//   dinv[i]  = d                          (lane 0)
//   deg[i]   = 0                          (lane 0 — reset for graph replay)
//   out[i,:] = xw[i,:] * d^2 + b          (self-loop message + bias)
// 16 threads per node (one float4 column group each). All 16 lanes of a node
// live in the same warp, so the deg read-then-reset is program-order safe.
// ---------------------------------------------------------------------------
__global__ void __launch_bounds__(256) fused_node_kernel(
    const float* __restrict__ b, float* __restrict__ out, int n)
{
    int idx = blockIdx.x * blockDim.x + threadIdx.x;
    int i = idx >> 4, c4 = idx & 15;
    if (i >= n) return;

    float dg = g_deg[i];                 // broadcast load within warp
    float di = rsqrtf(dg + 1.0f);
    if (c4 == 0) {
        g_dinv[i] = di;
        g_deg[i]  = 0.0f;                // reset for next replay
    }

    float s = di * di;
    float4 v  = ((const float4*)(g_xw + (size_t)i * D))[c4];
    float4 bb = ((const float4*)b)[c4];
    float4 o;
    o.x = v.x * s + bb.x;
    o.y = v.y * s + bb.y;
    o.z = v.z * s + bb.z;
    o.w = v.w * s + bb.w;
    ((float4*)(out + (size_t)i * D))[c4] = o;
}

// ---------------------------------------------------------------------------
// K3: edge scatter: out[dst] += xw[src] * dinv[src]*dinv[dst]
// 16 threads per edge, one red.global.add.v4.f32 per thread (16B, aligned).
// ---------------------------------------------------------------------------
__device__ __forceinline__ void red_add_v4(float* dp, float a, float b, float c, float d)
{
#if !defined(__CUDA_ARCH__) || __CUDA_ARCH__ >= 900
    asm volatile(
        "red.global.add.v4.f32 [%0], {%1, %2, %3, %4};"
        :: "l"(dp), "f"(a), "f"(b), "f"(c), "f"(d)
        : "memory");
#else
    atomicAdd(dp + 0, a);
    atomicAdd(dp + 1, b);
    atomicAdd(dp + 2, c);
    atomicAdd(dp + 3, d);
#endif
}

__global__ void __launch_bounds__(256) scatter_kernel(
    const int* __restrict__ ei, float* __restrict__ out, int E)
{
    unsigned int t = blockIdx.x * 256u + threadIdx.x;
    int e    = (int)(t >> 4);
    int lane = (int)(t & 15);
    if (e >= E) return;

    int s = __ldg(&ei[e]);
    int d = __ldg(&ei[E + e]);
    float c = g_dinv[s] * g_dinv[d];

    float4 v = ((const float4*)(g_xw + (size_t)s * D))[lane];
    float* dp = out + (size_t)d * D + lane * 4;

    red_add_v4(dp, v.x * c, v.y * c, v.z * c, v.w * c);
}

// ---------------------------------------------------------------------------
// Launch
// Inputs (metadata order): x [n*64] f32, edge_index [2*E] int32, W [64*64] f32,
//                          b [64] f32. Output: [n*64] f32.
// 4 launches total: gemm, deg_count, fused_node, scatter.
// ---------------------------------------------------------------------------
extern "C" void kernel_launch(void* const* d_in, const int* in_sizes, int n_in,
                              void* d_out, int out_size)
{
    const float* x  = (const float*)d_in[0];
    const int*   ei = (const int*)d_in[1];
    const float* W  = (const float*)d_in[2];
    const float* b  = (const float*)d_in[3];
    float*       out = (float*)d_out;

    const int n = in_sizes[0] / D;       // 100000
    const int E = in_sizes[1] / 2;       // 1600000

    // K0: projection
    gemm64_kernel<<<(n + 63) / 64, 256>>>(x, W, n);

    // K1: degree histogram (dst row)
    deg_count_kernel<<<(E + 255) / 256, 256>>>(ei + E, E);

    // K2: dinv + deg reset + self-loop/bias out init (fused)
    {
        int total = n * 16;
        fused_node_kernel<<<(total + 255) / 256, 256>>>(b, out, n);
    }

    // K3: edge scatter
    {
        long long total = (long long)E * 16;
        int blocks = (int)((total + 255) / 256);
        scatter_kernel<<<blocks, 256>>>(ei, out, E);
    }
}